// round 3
// baseline (speedup 1.0000x reference)
#include <cuda_runtime.h>
#include <cuda_bf16.h>
#include <stdint.h>

// Problem constants
#define BGRAPH 64
#define NNODE  2048
#define DDIM   256
#define NQ     16      // 12 class + 4 group queries
#define TOTN   (BGRAPH * NNODE)   // 131072

// ---------------- device scratch (allocation-free) ----------------
__device__ __align__(16) float gQ[NQ * DDIM];                 // pre-scaled queries
__device__ float gH[4 * 512];                                 // MLP hidden
__device__ __align__(16) float gS[(size_t)TOTN * NQ];         // scores -> probs (8 MB)
__device__ __align__(16) float gP[256 * NQ * DDIM];           // pooled partials (4 MB)

// =============================================================
// K0a: hidden = relu(q[g] @ w1[g] + b1[g])      grid (4,4) x 128
// =============================================================
__global__ void k0a_hidden(const float* __restrict__ gq, const float* __restrict__ w1,
                           const float* __restrict__ b1) {
    int g = blockIdx.x, part = blockIdx.y, t = threadIdx.x;
    __shared__ float q[256];
    q[t] = gq[g * 256 + t];
    q[t + 128] = gq[g * 256 + t + 128];
    __syncthreads();
    int j = part * 128 + t;                      // hidden index 0..511
    const float* w = w1 + (size_t)g * 256 * 512 + j;
    float acc = b1[g * 512 + j];
#pragma unroll 8
    for (int d = 0; d < 256; d++) acc = fmaf(q[d], w[(size_t)d * 512], acc);
    gH[g * 512 + j] = fmaxf(acc, 0.f);
}

// =============================================================
// K0b: class queries = (h @ w2 + b2) * (1/16); group rows too.
// grid (4,3) x 256
// =============================================================
__global__ void k0b_queries(const float* __restrict__ gq, const float* __restrict__ w2,
                            const float* __restrict__ b2) {
    int g = blockIdx.x, part = blockIdx.y, t = threadIdx.x;
    __shared__ float h[512];
    h[t] = gH[g * 512 + t];
    h[t + 256] = gH[g * 512 + t + 256];
    __syncthreads();
    int k = part * 256 + t;                      // 0..767
    const float* w = w2 + (size_t)g * 512 * 768 + k;
    float acc = b2[g * 768 + k];
#pragma unroll 8
    for (int hh = 0; hh < 512; hh++) acc = fmaf(h[hh], w[(size_t)hh * 768], acc);
    gQ[(g * 3 + (k >> 8)) * 256 + (k & 255)] = acc * 0.0625f;   // 1/sqrt(256)
    if (part == 0) gQ[(12 + g) * 256 + t] = gq[g * 256 + t] * 0.0625f;
}

// =============================================================
// K1: scores[n][c] = x[n] . Qscaled[c]  for all 16 queries.
// grid 512 x 256 (8 warps/block, 32 nodes/warp)
// Plain float4 math; queries in registers; 2-deep node prefetch;
// query-splitting butterfly reduction (17 shfl / node).
// =============================================================
__global__ void __launch_bounds__(256, 1) k1_scores(const float* __restrict__ X) {
    int wid = threadIdx.x >> 5, lane = threadIdx.x & 31;
    int gwarp = blockIdx.x * 8 + wid;
    int n0 = gwarp * 32;

    // lane owns dims d = lane*8 .. lane*8+7 of every query
    float4 q4[16][2];
    const float4* Qv = reinterpret_cast<const float4*>(gQ);
#pragma unroll
    for (int c = 0; c < 16; c++) {
        q4[c][0] = Qv[c * 64 + lane * 2];
        q4[c][1] = Qv[c * 64 + lane * 2 + 1];
    }

    const float4* X4 = reinterpret_cast<const float4*>(X);
    const unsigned FULL = 0xffffffffu;
    bool h4 = (lane & 16) != 0, h3 = (lane & 8) != 0, h2 = (lane & 4) != 0, h1 = (lane & 2) != 0;

    float4 xb[2][2];
#define LOADX(slot, nn) { const float4* p = X4 + (size_t)(nn) * 64 + lane * 2; \
                          xb[slot][0] = p[0]; xb[slot][1] = p[1]; }

    LOADX(0, n0 + 0); LOADX(1, n0 + 1);

#pragma unroll 1
    for (int i = 0; i < 32; i += 2) {
#pragma unroll
        for (int u = 0; u < 2; u++) {
            int n = n0 + i + u;
            float4 x0 = xb[u][0], x1 = xb[u][1];
            if (i + 2 + u < 32) { LOADX(u, n0 + i + 2 + u); }

            float s[16];
#pragma unroll
            for (int c = 0; c < 16; c++) {
                float4 a = q4[c][0], b = q4[c][1];
                float r = x0.x * a.x;
                r = fmaf(x0.y, a.y, r);
                r = fmaf(x0.z, a.z, r);
                r = fmaf(x0.w, a.w, r);
                r = fmaf(x1.x, b.x, r);
                r = fmaf(x1.y, b.y, r);
                r = fmaf(x1.z, b.z, r);
                r = fmaf(x1.w, b.w, r);
                s[c] = r;
            }
            // butterfly with query splitting: final lane holds query (lane>>1)&15
            float t8[8];
#pragma unroll
            for (int k = 0; k < 8; k++) {
                float snd = h4 ? s[k] : s[k + 8];
                float rcv = __shfl_xor_sync(FULL, snd, 16);
                t8[k] = (h4 ? s[k + 8] : s[k]) + rcv;
            }
            float t4[4];
#pragma unroll
            for (int k = 0; k < 4; k++) {
                float snd = h3 ? t8[k] : t8[k + 4];
                float rcv = __shfl_xor_sync(FULL, snd, 8);
                t4[k] = (h3 ? t8[k + 4] : t8[k]) + rcv;
            }
            float t2[2];
#pragma unroll
            for (int k = 0; k < 2; k++) {
                float snd = h2 ? t4[k] : t4[k + 2];
                float rcv = __shfl_xor_sync(FULL, snd, 4);
                t2[k] = (h2 ? t4[k + 2] : t4[k]) + rcv;
            }
            float snd = h1 ? t2[0] : t2[1];
            float rcv = __shfl_xor_sync(FULL, snd, 2);
            float t1 = (h1 ? t2[1] : t2[0]) + rcv;
            t1 += __shfl_xor_sync(FULL, t1, 1);
            float wv = __shfl_sync(FULL, t1, (lane & 15) << 1);
            if (lane < 16) gS[(size_t)n * 16 + lane] = wv;
        }
    }
#undef LOADX
}

// =============================================================
// K2: per-graph softmax over n, normalize gS in place, write attn12
// output (transposed, coalesced).  grid 64 x 256
// =============================================================
__global__ void k2_softmax(float* __restrict__ outAttn) {
    int b = blockIdx.x, t = threadIdx.x;
    int c = t & 15, r = t >> 4;
    float* S = gS + (size_t)b * NNODE * 16;
    __shared__ float red[16][17];
    __shared__ float mfin[16], rinv[16];
    __shared__ float T[128][17];

    // pass 1: max per c
    float m = -3.0e38f;
    for (int i = t; i < NNODE * 16; i += 256) m = fmaxf(m, S[i]);   // i&15 == c
    red[c][r] = m;
    __syncthreads();
    if (t < 16) {
        float mm = red[t][0];
#pragma unroll
        for (int k = 1; k < 16; k++) mm = fmaxf(mm, red[t][k]);
        mfin[t] = mm;
    }
    __syncthreads();

    // pass 2: exp & sum
    float mc = mfin[c];
    float sum = 0.f;
    for (int i = t; i < NNODE * 16; i += 256) {
        float p = __expf(S[i] - mc);
        S[i] = p;
        sum += p;
    }
    red[c][r] = sum;
    __syncthreads();
    if (t < 16) {
        float ss = 0.f;
#pragma unroll
        for (int k = 0; k < 16; k++) ss += red[t][k];
        rinv[t] = 1.f / ss;
    }
    __syncthreads();

    // pass 3: normalize in place + transposed write of attn12
    float ri = rinv[c];
    for (int nc = 0; nc < 16; nc++) {
#pragma unroll
        for (int k = 0; k < 8; k++) {
            int li = t + k * 256;               // 0..2047 within chunk
            int idx = nc * 2048 + li;
            float p = S[idx] * ri;              // li&15 == c, so ri matches
            S[idx] = p;
            T[li >> 4][c] = p;
        }
        __syncthreads();
#pragma unroll
        for (int cc = 0; cc < 6; cc++) {
            int ci = cc * 2 + (t >> 7);
            int nl = t & 127;
            outAttn[((size_t)b * 12 + ci) * NNODE + nc * 128 + nl] = T[nl][ci];
        }
        __syncthreads();
    }
}

// =============================================================
// K3: pooled[c][:] += attn[n][c] * x[n][:]
// grid 256 (=64 graphs x 4 chunks) x 256. Direct coalesced LDG,
// warp = 64 contiguous nodes, lane owns 8 dims, 2-deep prefetch.
// =============================================================
__global__ void __launch_bounds__(256, 1) k3_pool(const float* __restrict__ X) {
    int b = blockIdx.x >> 2, chunk = blockIdx.x & 3;
    int t = threadIdx.x, wid = t >> 5, lane = t & 31;
    int n0 = b * NNODE + chunk * 512 + wid * 64;   // this warp's 64 nodes

    const float4* X4 = reinterpret_cast<const float4*>(X);
    const float4* P4 = reinterpret_cast<const float4*>(gS);

    float4 acc[16][2];
#pragma unroll
    for (int c = 0; c < 16; c++) {
        acc[c][0] = make_float4(0.f, 0.f, 0.f, 0.f);
        acc[c][1] = make_float4(0.f, 0.f, 0.f, 0.f);
    }

    float4 xb[2][2];
    float4 pb[2][4];
#define LOADN(slot, nn) { const float4* p = X4 + (size_t)(nn) * 64 + lane * 2; \
                          xb[slot][0] = p[0]; xb[slot][1] = p[1]; \
                          const float4* pp = P4 + (size_t)(nn) * 4; \
                          pb[slot][0] = pp[0]; pb[slot][1] = pp[1]; \
                          pb[slot][2] = pp[2]; pb[slot][3] = pp[3]; }

    LOADN(0, n0 + 0); LOADN(1, n0 + 1);

#pragma unroll 1
    for (int i = 0; i < 64; i += 2) {
#pragma unroll
        for (int u = 0; u < 2; u++) {
            float4 x0 = xb[u][0], x1 = xb[u][1];
            float pr[16];
            ((float4*)pr)[0] = pb[u][0];
            ((float4*)pr)[1] = pb[u][1];
            ((float4*)pr)[2] = pb[u][2];
            ((float4*)pr)[3] = pb[u][3];
            if (i + 2 + u < 64) { LOADN(u, n0 + i + 2 + u); }
#pragma unroll
            for (int c = 0; c < 16; c++) {
                float pc = pr[c];
                acc[c][0].x = fmaf(pc, x0.x, acc[c][0].x);
                acc[c][0].y = fmaf(pc, x0.y, acc[c][0].y);
                acc[c][0].z = fmaf(pc, x0.z, acc[c][0].z);
                acc[c][0].w = fmaf(pc, x0.w, acc[c][0].w);
                acc[c][1].x = fmaf(pc, x1.x, acc[c][1].x);
                acc[c][1].y = fmaf(pc, x1.y, acc[c][1].y);
                acc[c][1].z = fmaf(pc, x1.z, acc[c][1].z);
                acc[c][1].w = fmaf(pc, x1.w, acc[c][1].w);
            }
        }
    }
#undef LOADN

    // block reduce across 8 warps into smem
    __shared__ float red[4096];
    for (int w = 0; w < 8; w++) {
        if (wid == w) {
#pragma unroll
            for (int c = 0; c < 16; c++) {
                int d = c * 256 + lane * 8;
                if (w == 0) {
                    red[d + 0] = acc[c][0].x; red[d + 1] = acc[c][0].y;
                    red[d + 2] = acc[c][0].z; red[d + 3] = acc[c][0].w;
                    red[d + 4] = acc[c][1].x; red[d + 5] = acc[c][1].y;
                    red[d + 6] = acc[c][1].z; red[d + 7] = acc[c][1].w;
                } else {
                    red[d + 0] += acc[c][0].x; red[d + 1] += acc[c][0].y;
                    red[d + 2] += acc[c][0].z; red[d + 3] += acc[c][0].w;
                    red[d + 4] += acc[c][1].x; red[d + 5] += acc[c][1].y;
                    red[d + 6] += acc[c][1].z; red[d + 7] += acc[c][1].w;
                }
            }
        }
        __syncthreads();
    }
    float* gp = gP + (size_t)blockIdx.x * 4096;
    for (int i = t; i < 4096; i += 256) gp[i] = red[i];
}

// =============================================================
// K4: combine partials, LayerNorm per class, 2-layer heads, logits.
// grid 64 x 256
// =============================================================
__global__ void k4_heads(float* __restrict__ out,
                         const float* __restrict__ ln12g, const float* __restrict__ ln12b,
                         const float* __restrict__ w12a, const float* __restrict__ b12a,
                         const float* __restrict__ w12b, const float* __restrict__ b12b,
                         const float* __restrict__ ln4g, const float* __restrict__ ln4b,
                         const float* __restrict__ w4a, const float* __restrict__ b4a,
                         const float* __restrict__ w4b, const float* __restrict__ b4b) {
    int b = blockIdx.x, t = threadIdx.x;
    __shared__ float pool[4096];        // [c][d]
    __shared__ float xnT[256 * 16];     // [d][c]
    __shared__ float r1[16][17], r2[16][17];
    __shared__ float muv[16][2];
    __shared__ float yred[16][128];

    for (int i = t; i < 4096; i += 256) {
        float v = 0.f;
#pragma unroll
        for (int ch = 0; ch < 4; ch++) v += gP[(size_t)(b * 4 + ch) * 4096 + i];
        pool[i] = v;
    }
    __syncthreads();
    {
        int c = t >> 4, seg = t & 15;
        float s = 0.f, s2 = 0.f;
#pragma unroll
        for (int k = 0; k < 16; k++) {
            float v = pool[c * 256 + seg * 16 + k];
            s += v; s2 += v * v;
        }
        r1[c][seg] = s; r2[c][seg] = s2;
    }
    __syncthreads();
    if (t < 16) {
        float s = 0.f, s2 = 0.f;
#pragma unroll
        for (int k = 0; k < 16; k++) { s += r1[t][k]; s2 += r2[t][k]; }
        float mu = s * (1.f / 256.f);
        float var = s2 * (1.f / 256.f) - mu * mu;
        muv[t][0] = mu;
        muv[t][1] = rsqrtf(var + 1e-5f);
    }
    __syncthreads();
    for (int i = t; i < 4096; i += 256) {
        int c = i >> 8, d = i & 255;
        float g  = (c < 12) ? ln12g[d] : ln4g[d];
        float be = (c < 12) ? ln12b[d] : ln4b[d];
        xnT[d * 16 + c] = (pool[i] - muv[c][0]) * muv[c][1] * g + be;
    }
    __syncthreads();

    // GEMV1: y[c][j] = relu(sum_d xn[c][d] * wa[d][j] + ba[j])
    {
        int j = t & 127, half = t >> 7;
        float a12[12], a4[4];
#pragma unroll
        for (int c = 0; c < 12; c++) a12[c] = 0.f;
#pragma unroll
        for (int c = 0; c < 4; c++) a4[c] = 0.f;
        int d0 = half * 128;
        for (int d = d0; d < d0 + 128; d++) {
            float wa12 = w12a[d * 128 + j];
            float wa4 = w4a[d * 128 + j];
            const float4* xr = (const float4*)&xnT[d * 16];
            float4 x0 = xr[0], x1 = xr[1], x2 = xr[2], x3 = xr[3];
            a12[0] = fmaf(x0.x, wa12, a12[0]); a12[1] = fmaf(x0.y, wa12, a12[1]);
            a12[2] = fmaf(x0.z, wa12, a12[2]); a12[3] = fmaf(x0.w, wa12, a12[3]);
            a12[4] = fmaf(x1.x, wa12, a12[4]); a12[5] = fmaf(x1.y, wa12, a12[5]);
            a12[6] = fmaf(x1.z, wa12, a12[6]); a12[7] = fmaf(x1.w, wa12, a12[7]);
            a12[8] = fmaf(x2.x, wa12, a12[8]); a12[9] = fmaf(x2.y, wa12, a12[9]);
            a12[10] = fmaf(x2.z, wa12, a12[10]); a12[11] = fmaf(x2.w, wa12, a12[11]);
            a4[0] = fmaf(x3.x, wa4, a4[0]); a4[1] = fmaf(x3.y, wa4, a4[1]);
            a4[2] = fmaf(x3.z, wa4, a4[2]); a4[3] = fmaf(x3.w, wa4, a4[3]);
        }
        if (half == 0) {
#pragma unroll
            for (int c = 0; c < 12; c++) yred[c][j] = a12[c];
#pragma unroll
            for (int c = 0; c < 4; c++) yred[12 + c][j] = a4[c];
        }
        __syncthreads();
        if (half == 1) {
            float ba12 = b12a[j], ba4 = b4a[j];
#pragma unroll
            for (int c = 0; c < 12; c++) yred[c][j] = fmaxf(yred[c][j] + a12[c] + ba12, 0.f);
#pragma unroll
            for (int c = 0; c < 4; c++) yred[12 + c][j] = fmaxf(yred[12 + c][j] + a4[c] + ba4, 0.f);
        }
        __syncthreads();
    }

    // logits: 8 threads per class
    if (t < 128) {
        int c = t >> 3, jl = t & 7;
        const float* wb = (c < 12) ? w12b : w4b;
        float a = 0.f;
#pragma unroll
        for (int j = jl; j < 128; j += 8) a = fmaf(yred[c][j], wb[j], a);
        r1[c][jl] = a;
    }
    __syncthreads();
    if (t < 16) {
        float a = 0.f;
#pragma unroll
        for (int k = 0; k < 8; k++) a += r1[t][k];
        if (t < 12) out[b * 12 + t] = a + b12b[0];
        else        out[768 + b * 4 + (t - 12)] = a + b4b[0];
    }
}

// =============================================================
// launch
// =============================================================
extern "C" void kernel_launch(void* const* d_in, const int* in_sizes, int n_in,
                              void* d_out, int out_size) {
    const float* X      = (const float*)d_in[0];
    // d_in[1] = batch (int64) -- equal-size sorted segments: unused
    const float* gq     = (const float*)d_in[2];
    const float* w1     = (const float*)d_in[3];
    const float* b1     = (const float*)d_in[4];
    const float* w2     = (const float*)d_in[5];
    const float* b2     = (const float*)d_in[6];
    const float* ln12g  = (const float*)d_in[7];
    const float* ln12b  = (const float*)d_in[8];
    const float* w12a   = (const float*)d_in[9];
    const float* b12a   = (const float*)d_in[10];
    const float* w12b   = (const float*)d_in[11];
    const float* b12b   = (const float*)d_in[12];
    const float* ln4g   = (const float*)d_in[13];
    const float* ln4b   = (const float*)d_in[14];
    const float* w4a    = (const float*)d_in[15];
    const float* b4a    = (const float*)d_in[16];
    const float* w4b    = (const float*)d_in[17];
    const float* b4b    = (const float*)d_in[18];

    float* out = (float*)d_out;
    float* outAttn = out + 768 + 256;   // logits12[64*12], logits4[64*4], attn12[64*12*2048]

    k0a_hidden<<<dim3(4, 4), 128>>>(gq, w1, b1);
    k0b_queries<<<dim3(4, 3), 256>>>(gq, w2, b2);
    k1_scores<<<512, 256>>>(X);
    k2_softmax<<<64, 256>>>(outAttn);
    k3_pool<<<256, 256>>>(X);
    k4_heads<<<64, 256>>>(out, ln12g, ln12b, w12a, b12a, w12b, b12b,
                          ln4g, ln4b, w4a, b4a, w4b, b4b);
}

// round 4
// speedup vs baseline: 1.9159x; 1.9159x over previous
#include <cuda_runtime.h>
#include <cuda_bf16.h>
#include <stdint.h>

// Problem constants
#define BGRAPH 64
#define NNODE  2048
#define DDIM   256
#define NQ     16      // 12 class + 4 group queries
#define TOTN   (BGRAPH * NNODE)   // 131072

typedef unsigned long long u64;

// ---------------- device scratch (allocation-free) ----------------
__device__ __align__(16) float gQ[NQ * DDIM];                 // pre-scaled queries
__device__ float gH[4 * 512];                                 // MLP hidden
__device__ __align__(16) float gS[(size_t)TOTN * NQ];         // scores -> probs (8 MB)
__device__ __align__(16) float gP[256 * NQ * DDIM];           // pooled partials (4 MB)
__device__ float gM4[256 * 16];                               // per-chunk max
__device__ float gZ4[256 * 16];                               // per-chunk expsum
__device__ float gMg[64 * 16];                                // global max per (b,c)
__device__ float gRg[64 * 16];                                // 1/Z per (b,c)

// ---------------- f32x2 helpers ----------------
__device__ __forceinline__ u64 f2fma(u64 a, u64 b, u64 c) {
    u64 d; asm("fma.rn.f32x2 %0, %1, %2, %3;" : "=l"(d) : "l"(a), "l"(b), "l"(c)); return d;
}
__device__ __forceinline__ u64 f2mul(u64 a, u64 b) {
    u64 d; asm("mul.rn.f32x2 %0, %1, %2;" : "=l"(d) : "l"(a), "l"(b)); return d;
}
__device__ __forceinline__ float2 u2f(u64 a) {
    float2 f; asm("mov.b64 {%0, %1}, %2;" : "=f"(f.x), "=f"(f.y) : "l"(a)); return f;
}
__device__ __forceinline__ u64 splat2(float v) {
    u64 d; asm("mov.b64 %0, {%1, %1};" : "=l"(d) : "f"(v)); return d;
}

// ---------------- cp.async helpers ----------------
__device__ __forceinline__ void cp16(void* dst_smem, const void* src_gmem) {
    unsigned sa = (unsigned)__cvta_generic_to_shared(dst_smem);
    asm volatile("cp.async.cg.shared.global [%0], [%1], 16;" :: "r"(sa), "l"(src_gmem));
}
#define CP_COMMIT() asm volatile("cp.async.commit_group;")
#define CP_WAIT1()  asm volatile("cp.async.wait_group 1;")
#define CP_WAIT0()  asm volatile("cp.async.wait_group 0;")

// =============================================================
// K0a: hidden = relu(q[g] @ w1[g] + b1[g])
// grid (4 g, 4 jq) x 1024 threads = (128 j x 8 ksplit)
// =============================================================
__global__ void __launch_bounds__(1024) k0a_hidden(const float* __restrict__ gq,
                                                   const float* __restrict__ w1,
                                                   const float* __restrict__ b1) {
    int g = blockIdx.x, jq = blockIdx.y, t = threadIdx.x;
    int jl = t & 127, kp = t >> 7;
    __shared__ float q[256];
    __shared__ float part[8][128];
    if (t < 256) q[t] = gq[g * 256 + t];
    __syncthreads();
    int j = jq * 128 + jl;
    const float* w = w1 + (size_t)g * 256 * 512 + (size_t)(kp * 32) * 512 + j;
    float acc = 0.f;
#pragma unroll 8
    for (int d = 0; d < 32; d++) acc = fmaf(q[kp * 32 + d], w[(size_t)d * 512], acc);
    part[kp][jl] = acc;
    __syncthreads();
    if (t < 128) {
        float s = 0.f;
#pragma unroll
        for (int k = 0; k < 8; k++) s += part[k][t];
        int jj = jq * 128 + t;
        gH[g * 512 + jj] = fmaxf(s + b1[g * 512 + jj], 0.f);
    }
}

// =============================================================
// K0b: class queries = (h @ w2 + b2) / 16; group rows too.
// grid (4 g, 6 kq) x 1024 threads = (128 k x 8 hsplit)
// =============================================================
__global__ void __launch_bounds__(1024) k0b_queries(const float* __restrict__ gq,
                                                    const float* __restrict__ w2,
                                                    const float* __restrict__ b2) {
    int g = blockIdx.x, kq = blockIdx.y, t = threadIdx.x;
    int kl = t & 127, hp = t >> 7;
    __shared__ float h[512];
    __shared__ float part[8][128];
    if (t < 512) h[t] = gH[g * 512 + t];
    __syncthreads();
    int k = kq * 128 + kl;
    const float* w = w2 + (size_t)g * 512 * 768 + (size_t)(hp * 64) * 768 + k;
    float acc = 0.f;
#pragma unroll 8
    for (int hh = 0; hh < 64; hh++) acc = fmaf(h[hp * 64 + hh], w[(size_t)hh * 768], acc);
    part[hp][kl] = acc;
    __syncthreads();
    if (t < 128) {
        float s = 0.f;
#pragma unroll
        for (int kk = 0; kk < 8; kk++) s += part[kk][t];
        int kg = kq * 128 + t;
        float val = (s + b2[g * 768 + kg]) * 0.0625f;   // 1/sqrt(256)
        gQ[(g * 3 + (kg >> 8)) * 256 + (kg & 255)] = val;
    }
    if (kq == 0 && t >= 256 && t < 512) {
        int d = t - 256;
        gQ[(12 + g) * 256 + d] = gq[g * 256 + d] * 0.0625f;
    }
}

// =============================================================
// K1: scores[n][c] = x[n] . Qscaled[c].
// grid 2048 x 128. Warp pairs share 32-node range; each warp does
// 8 queries (qhalf). Lane owns dims {4l..4l+3, 128+4l..128+4l+3}.
// f32x2 packed FMA; depth-4 node prefetch; 8-query butterfly.
// =============================================================
__global__ void __launch_bounds__(128) k1_scores(const float* __restrict__ X) {
    int wid = threadIdx.x >> 5, lane = threadIdx.x & 31;
    int gwarp = blockIdx.x * 4 + wid;
    int n0 = (gwarp >> 1) * 32;
    int qh = gwarp & 1;

    // load 8 queries: q[j][0..3] f32x2 pairs for dims (4l,4l+1),(4l+2,4l+3),
    // (128+4l,128+4l+1),(128+4l+2,128+4l+3)
    u64 q[8][4];
    const ulonglong2* Qu = reinterpret_cast<const ulonglong2*>(gQ);
#pragma unroll
    for (int j = 0; j < 8; j++) {
        int c = qh * 8 + j;
        ulonglong2 a = Qu[c * 64 + lane];
        ulonglong2 b = Qu[c * 64 + 32 + lane];
        q[j][0] = a.x; q[j][1] = a.y; q[j][2] = b.x; q[j][3] = b.y;
    }

    const ulonglong2* px = reinterpret_cast<const ulonglong2*>(X) + (size_t)n0 * 64 + lane;
    const unsigned FULL = 0xffffffffu;
    bool b4 = (lane & 16) != 0, b3 = (lane & 8) != 0, b2 = (lane & 4) != 0;

    u64 xb[4][4];
#define LOADX(slot, rel) { ulonglong2 a = px[(rel) * 64]; ulonglong2 b = px[(rel) * 64 + 32]; \
                           xb[slot][0] = a.x; xb[slot][1] = a.y; xb[slot][2] = b.x; xb[slot][3] = b.y; }

    LOADX(0, 0); LOADX(1, 1); LOADX(2, 2); LOADX(3, 3);

#pragma unroll 1
    for (int i = 0; i < 32; i += 4) {
#pragma unroll
        for (int u = 0; u < 4; u++) {
            int n = n0 + i + u;
            u64 x0 = xb[u][0], x1 = xb[u][1], x2 = xb[u][2], x3 = xb[u][3];
            if (i + 4 + u < 32) { LOADX(u, i + 4 + u); }

            float s[8];
#pragma unroll
            for (int j = 0; j < 8; j++) {
                u64 a = f2mul(x0, q[j][0]);
                a = f2fma(x1, q[j][1], a);
                a = f2fma(x2, q[j][2], a);
                a = f2fma(x3, q[j][3], a);
                float2 f = u2f(a);
                s[j] = f.x + f.y;
            }
            // butterfly: final lane holds query (lane>>2)&7
            float t4[4];
#pragma unroll
            for (int k = 0; k < 4; k++) {
                float snd = b4 ? s[k] : s[k + 4];
                float rcv = __shfl_xor_sync(FULL, snd, 16);
                t4[k] = (b4 ? s[k + 4] : s[k]) + rcv;
            }
            float t2[2];
#pragma unroll
            for (int k = 0; k < 2; k++) {
                float snd = b3 ? t4[k] : t4[k + 2];
                float rcv = __shfl_xor_sync(FULL, snd, 8);
                t2[k] = (b3 ? t4[k + 2] : t4[k]) + rcv;
            }
            float snd = b2 ? t2[0] : t2[1];
            float rcv = __shfl_xor_sync(FULL, snd, 4);
            float t1 = (b2 ? t2[1] : t2[0]) + rcv;
            t1 += __shfl_xor_sync(FULL, t1, 2);
            t1 += __shfl_xor_sync(FULL, t1, 1);
            float wv = __shfl_sync(FULL, t1, (lane & 7) << 2);
            if (lane < 8) gS[(size_t)n * 16 + qh * 8 + lane] = wv;
        }
    }
#undef LOADX
}

// =============================================================
// K2a: per-(b,chunk,c) max and expsum over 512 nodes. grid 256 x 256
// =============================================================
__global__ void k2a_stats() {
    int bi = blockIdx.x, t = threadIdx.x;
    int b = bi >> 2, ch = bi & 3;
    const float* S = gS + ((size_t)(b * NNODE + ch * 512)) * 16;
    int c = t & 15, r = t >> 4;
    __shared__ float red[16][17];
    __shared__ float mf[16];

    float m = -3.0e38f;
    for (int i = t; i < 512 * 16; i += 256) m = fmaxf(m, S[i]);   // i&15 == c
    red[c][r] = m;
    __syncthreads();
    if (t < 16) {
        float mm = red[t][0];
#pragma unroll
        for (int k = 1; k < 16; k++) mm = fmaxf(mm, red[t][k]);
        mf[t] = mm;
    }
    __syncthreads();
    float mc = mf[c];
    float sum = 0.f;
    for (int i = t; i < 512 * 16; i += 256) sum += __expf(S[i] - mc);
    red[c][r] = sum;
    __syncthreads();
    if (t < 16) {
        float Z = 0.f;
#pragma unroll
        for (int k = 0; k < 16; k++) Z += red[t][k];
        gM4[bi * 16 + t] = mf[t];
        gZ4[bi * 16 + t] = Z;
    }
}

// =============================================================
// K2b: combine chunk stats -> global m, 1/Z. 1 block x 1024
// =============================================================
__global__ void __launch_bounds__(1024) k2b_combine() {
    int t = threadIdx.x;
    int b = t >> 4, c = t & 15;
    float m = -3.0e38f;
#pragma unroll
    for (int ch = 0; ch < 4; ch++) m = fmaxf(m, gM4[(b * 4 + ch) * 16 + c]);
    float Z = 0.f;
#pragma unroll
    for (int ch = 0; ch < 4; ch++)
        Z += gZ4[(b * 4 + ch) * 16 + c] * __expf(gM4[(b * 4 + ch) * 16 + c] - m);
    gMg[b * 16 + c] = m;
    gRg[b * 16 + c] = 1.f / Z;
}

// =============================================================
// K2c: normalize gS in place to probs + write attn12 output
// (transposed, coalesced). grid 256 x 256
// =============================================================
__global__ void k2c_norm(float* __restrict__ outAttn) {
    int bi = blockIdx.x, t = threadIdx.x;
    int b = bi >> 2, ch = bi & 3;
    float* S = gS + ((size_t)(b * NNODE + ch * 512)) * 16;
    __shared__ float T[128][17];
    __shared__ float mv[16], rv[16];
    if (t < 16) { mv[t] = gMg[b * 16 + t]; rv[t] = gRg[b * 16 + t]; }
    __syncthreads();
    int c = t & 15;
    float mc = mv[c], rc = rv[c];

    for (int tile = 0; tile < 4; tile++) {
#pragma unroll
        for (int k = 0; k < 8; k++) {
            int li = t + k * 256;               // 0..2047; li&15 == c
            int idx = tile * 2048 + li;
            float p = __expf(S[idx] - mc) * rc;
            S[idx] = p;
            T[li >> 4][c] = p;
        }
        __syncthreads();
#pragma unroll
        for (int cc = 0; cc < 6; cc++) {
            int ci = cc * 2 + (t >> 7);
            int nl = t & 127;
            outAttn[((size_t)b * 12 + ci) * NNODE + ch * 512 + tile * 128 + nl] = T[nl][ci];
        }
        __syncthreads();
    }
}

// =============================================================
// K3: pooled[c][:] += p[n][c] * x[n][:]
// grid 256 (=64 b x 4 chunks) x 256. cp.async double-buffered
// 16-node tiles. Warp w: c-half = w>>2, nodes (w&3)*4..+4 per tile.
// Lane owns dims {4l..4l+3, 128+4l..+3}. acc in f32x2 regs.
// =============================================================
__global__ void __launch_bounds__(256) k3_pool(const float* __restrict__ X) {
    int bi = blockIdx.x;
    int b = bi >> 2, ch = bi & 3;
    int t = threadIdx.x, wid = t >> 5, lane = t & 31;
    int chh = wid >> 2;                         // c-half (0: c0-7, 1: c8-15)
    int ng = wid & 3;                           // node group within tile
    int node_base = b * NNODE + ch * 512;

    __shared__ float4 Xs[2][1024];              // 2 x 16 nodes x 64 float4
    __shared__ float4 Ps[2][64];                // 2 x 16 nodes x 4 float4

    u64 acc[8][4];
#pragma unroll
    for (int c = 0; c < 8; c++)
#pragma unroll
        for (int k = 0; k < 4; k++) acc[c][k] = 0ull;

    const float4* Xg = reinterpret_cast<const float4*>(X);
    const float4* Pg = reinterpret_cast<const float4*>(gS);

#define LOADT(tile, buf) { \
        const float4* src = Xg + (size_t)(node_base + (tile) * 16) * 64; \
        cp16(&Xs[buf][t], &src[t]); \
        cp16(&Xs[buf][t + 256], &src[t + 256]); \
        cp16(&Xs[buf][t + 512], &src[t + 512]); \
        cp16(&Xs[buf][t + 768], &src[t + 768]); \
        if (t < 64) cp16(&Ps[buf][t], &Pg[(size_t)(node_base + (tile) * 16) * 4 + t]); \
        CP_COMMIT(); }

    LOADT(0, 0);
#pragma unroll 1
    for (int tile = 0; tile < 32; tile++) {
        int buf = tile & 1;
        if (tile + 1 < 32) { LOADT(tile + 1, buf ^ 1); CP_WAIT1(); }
        else               { CP_WAIT0(); }
        __syncthreads();

#pragma unroll
        for (int j = 0; j < 4; j++) {
            int node = ng * 4 + j;
            const ulonglong2* xp = reinterpret_cast<const ulonglong2*>(&Xs[buf][node * 64]);
            ulonglong2 xa = xp[lane];
            ulonglong2 xc = xp[32 + lane];
            float4 pa = Ps[buf][node * 4 + chh * 2];
            float4 pb = Ps[buf][node * 4 + chh * 2 + 1];
            float pv[8] = {pa.x, pa.y, pa.z, pa.w, pb.x, pb.y, pb.z, pb.w};
#pragma unroll
            for (int c = 0; c < 8; c++) {
                u64 p2 = splat2(pv[c]);
                acc[c][0] = f2fma(p2, xa.x, acc[c][0]);
                acc[c][1] = f2fma(p2, xa.y, acc[c][1]);
                acc[c][2] = f2fma(p2, xc.x, acc[c][2]);
                acc[c][3] = f2fma(p2, xc.y, acc[c][3]);
            }
        }
        __syncthreads();
    }
#undef LOADT

    // block reduce: warps 0-3 partials for c0-7, warps 4-7 for c8-15
    float* red = (float*)Xs;
    for (int w = 0; w < 8; w++) {
        if (wid == w) {
#pragma unroll
            for (int c = 0; c < 8; c++) {
                int cg = chh * 8 + c;
                float2 v0 = u2f(acc[c][0]), v1 = u2f(acc[c][1]);
                float2 v2 = u2f(acc[c][2]), v3 = u2f(acc[c][3]);
                int d0 = cg * 256 + lane * 4;
                int d1 = cg * 256 + 128 + lane * 4;
                if ((w & 3) == 0) {
                    red[d0 + 0] = v0.x; red[d0 + 1] = v0.y; red[d0 + 2] = v1.x; red[d0 + 3] = v1.y;
                    red[d1 + 0] = v2.x; red[d1 + 1] = v2.y; red[d1 + 2] = v3.x; red[d1 + 3] = v3.y;
                } else {
                    red[d0 + 0] += v0.x; red[d0 + 1] += v0.y; red[d0 + 2] += v1.x; red[d0 + 3] += v1.y;
                    red[d1 + 0] += v2.x; red[d1 + 1] += v2.y; red[d1 + 2] += v3.x; red[d1 + 3] += v3.y;
                }
            }
        }
        __syncthreads();
    }
    float* gp = gP + (size_t)bi * 4096;
    for (int i = t; i < 4096; i += 256) gp[i] = red[i];
}

// =============================================================
// K4: combine partials, LayerNorm per class, 2-layer heads, logits.
// grid 64 x 256
// =============================================================
__global__ void k4_heads(float* __restrict__ out,
                         const float* __restrict__ ln12g, const float* __restrict__ ln12b,
                         const float* __restrict__ w12a, const float* __restrict__ b12a,
                         const float* __restrict__ w12b, const float* __restrict__ b12b,
                         const float* __restrict__ ln4g, const float* __restrict__ ln4b,
                         const float* __restrict__ w4a, const float* __restrict__ b4a,
                         const float* __restrict__ w4b, const float* __restrict__ b4b) {
    int b = blockIdx.x, t = threadIdx.x;
    __shared__ float pool[4096];        // [c][d]
    __shared__ float xnT[256 * 16];     // [d][c]
    __shared__ float r1[16][17], r2[16][17];
    __shared__ float muv[16][2];
    __shared__ float yred[16][128];

    for (int i = t; i < 4096; i += 256) {
        float v = 0.f;
#pragma unroll
        for (int ch = 0; ch < 4; ch++) v += gP[(size_t)(b * 4 + ch) * 4096 + i];
        pool[i] = v;
    }
    __syncthreads();
    {
        int c = t >> 4, seg = t & 15;
        float s = 0.f, s2 = 0.f;
#pragma unroll
        for (int k = 0; k < 16; k++) {
            float v = pool[c * 256 + seg * 16 + k];
            s += v; s2 += v * v;
        }
        r1[c][seg] = s; r2[c][seg] = s2;
    }
    __syncthreads();
    if (t < 16) {
        float s = 0.f, s2 = 0.f;
#pragma unroll
        for (int k = 0; k < 16; k++) { s += r1[t][k]; s2 += r2[t][k]; }
        float mu = s * (1.f / 256.f);
        float var = s2 * (1.f / 256.f) - mu * mu;
        muv[t][0] = mu;
        muv[t][1] = rsqrtf(var + 1e-5f);
    }
    __syncthreads();
    for (int i = t; i < 4096; i += 256) {
        int c = i >> 8, d = i & 255;
        float g  = (c < 12) ? ln12g[d] : ln4g[d];
        float be = (c < 12) ? ln12b[d] : ln4b[d];
        xnT[d * 16 + c] = (pool[i] - muv[c][0]) * muv[c][1] * g + be;
    }
    __syncthreads();

    // GEMV1: y[c][j] = relu(sum_d xn[c][d] * wa[d][j] + ba[j])
    {
        int j = t & 127, half = t >> 7;
        float a12[12], a4[4];
#pragma unroll
        for (int c = 0; c < 12; c++) a12[c] = 0.f;
#pragma unroll
        for (int c = 0; c < 4; c++) a4[c] = 0.f;
        int d0 = half * 128;
#pragma unroll 4
        for (int d = d0; d < d0 + 128; d++) {
            float wa12 = w12a[d * 128 + j];
            float wa4 = w4a[d * 128 + j];
            const float4* xr = (const float4*)&xnT[d * 16];
            float4 x0 = xr[0], x1 = xr[1], x2 = xr[2], x3 = xr[3];
            a12[0] = fmaf(x0.x, wa12, a12[0]); a12[1] = fmaf(x0.y, wa12, a12[1]);
            a12[2] = fmaf(x0.z, wa12, a12[2]); a12[3] = fmaf(x0.w, wa12, a12[3]);
            a12[4] = fmaf(x1.x, wa12, a12[4]); a12[5] = fmaf(x1.y, wa12, a12[5]);
            a12[6] = fmaf(x1.z, wa12, a12[6]); a12[7] = fmaf(x1.w, wa12, a12[7]);
            a12[8] = fmaf(x2.x, wa12, a12[8]); a12[9] = fmaf(x2.y, wa12, a12[9]);
            a12[10] = fmaf(x2.z, wa12, a12[10]); a12[11] = fmaf(x2.w, wa12, a12[11]);
            a4[0] = fmaf(x3.x, wa4, a4[0]); a4[1] = fmaf(x3.y, wa4, a4[1]);
            a4[2] = fmaf(x3.z, wa4, a4[2]); a4[3] = fmaf(x3.w, wa4, a4[3]);
        }
        if (half == 0) {
#pragma unroll
            for (int c = 0; c < 12; c++) yred[c][j] = a12[c];
#pragma unroll
            for (int c = 0; c < 4; c++) yred[12 + c][j] = a4[c];
        }
        __syncthreads();
        if (half == 1) {
            float ba12 = b12a[j], ba4 = b4a[j];
#pragma unroll
            for (int c = 0; c < 12; c++) yred[c][j] = fmaxf(yred[c][j] + a12[c] + ba12, 0.f);
#pragma unroll
            for (int c = 0; c < 4; c++) yred[12 + c][j] = fmaxf(yred[12 + c][j] + a4[c] + ba4, 0.f);
        }
        __syncthreads();
    }

    // logits: 8 threads per class
    if (t < 128) {
        int c = t >> 3, jl = t & 7;
        const float* wb = (c < 12) ? w12b : w4b;
        float a = 0.f;
#pragma unroll
        for (int j = jl; j < 128; j += 8) a = fmaf(yred[c][j], wb[j], a);
        r1[c][jl] = a;
    }
    __syncthreads();
    if (t < 16) {
        float a = 0.f;
#pragma unroll
        for (int k = 0; k < 8; k++) a += r1[t][k];
        if (t < 12) out[b * 12 + t] = a + b12b[0];
        else        out[768 + b * 4 + (t - 12)] = a + b4b[0];
    }
}

// =============================================================
// launch
// =============================================================
extern "C" void kernel_launch(void* const* d_in, const int* in_sizes, int n_in,
                              void* d_out, int out_size) {
    const float* X      = (const float*)d_in[0];
    // d_in[1] = batch (int64) -- equal-size sorted segments: unused
    const float* gq     = (const float*)d_in[2];
    const float* w1     = (const float*)d_in[3];
    const float* b1     = (const float*)d_in[4];
    const float* w2     = (const float*)d_in[5];
    const float* b2     = (const float*)d_in[6];
    const float* ln12g  = (const float*)d_in[7];
    const float* ln12b  = (const float*)d_in[8];
    const float* w12a   = (const float*)d_in[9];
    const float* b12a   = (const float*)d_in[10];
    const float* w12b   = (const float*)d_in[11];
    const float* b12b   = (const float*)d_in[12];
    const float* ln4g   = (const float*)d_in[13];
    const float* ln4b   = (const float*)d_in[14];
    const float* w4a    = (const float*)d_in[15];
    const float* b4a    = (const float*)d_in[16];
    const float* w4b    = (const float*)d_in[17];
    const float* b4b    = (const float*)d_in[18];

    float* out = (float*)d_out;
    float* outAttn = out + 768 + 256;   // logits12[64*12], logits4[64*4], attn12[64*12*2048]

    k0a_hidden<<<dim3(4, 4), 1024>>>(gq, w1, b1);
    k0b_queries<<<dim3(4, 6), 1024>>>(gq, w2, b2);
    k1_scores<<<2048, 128>>>(X);
    k2a_stats<<<256, 256>>>();
    k2b_combine<<<1, 1024>>>();
    k2c_norm<<<256, 256>>>(outAttn);
    k3_pool<<<256, 256>>>(X);
    k4_heads<<<64, 256>>>(out, ln12g, ln12b, w12a, b12a, w12b, b12b,
                          ln4g, ln4b, w4a, b4a, w4b, b4b);
}